// round 1
// baseline (speedup 1.0000x reference)
#include <cuda_runtime.h>
#include <math.h>

#define S   2048
#define D   1024
#define H   16
#define HD  64
#define MM  4096
#define LAY 4

// ---------------- scratch (device globals: no allocation allowed) ----------------
__device__ float g_x[S * D];
__device__ float g_h[S * D];
__device__ float g_q[S * D];
__device__ float g_k[S * D];
__device__ float g_v[S * D];
__device__ float g_ctx[S * D];
__device__ float g_y[S * MM];

// ---------------- embedding + sinusoidal positional encoding ----------------
__global__ __launch_bounds__(256) void embed_kernel(const int* __restrict__ ids,
                                                    const float* __restrict__ emb,
                                                    float* __restrict__ x) {
    int s = blockIdx.x;
    int id = ids[s];
    const double c = -9.210340371976184 / 1024.0;  // -ln(10000)/D
    for (int d = threadIdx.x; d < D; d += 256) {
        int p2 = d & ~1;                       // 2*(d/2)
        double freq = exp((double)p2 * c);
        double phase = (double)s * freq;
        double pe = (d & 1) ? cos(phase) : sin(phase);
        x[s * D + d] = emb[id * D + d] + (float)pe;
    }
}

// ---------------- LayerNorm (one block per row of 1024) ----------------
__global__ __launch_bounds__(256) void ln_kernel(const float* __restrict__ x,
                                                 const float* __restrict__ sc,
                                                 const float* __restrict__ bi,
                                                 float* __restrict__ out) {
    __shared__ float ssum[256], ssq[256];
    int s = blockIdx.x, tid = threadIdx.x;
    float4 v = ((const float4*)(x + s * D))[tid];
    ssum[tid] = v.x + v.y + v.z + v.w;
    ssq[tid]  = v.x * v.x + v.y * v.y + v.z * v.z + v.w * v.w;
    __syncthreads();
#pragma unroll
    for (int off = 128; off > 0; off >>= 1) {
        if (tid < off) { ssum[tid] += ssum[tid + off]; ssq[tid] += ssq[tid + off]; }
        __syncthreads();
    }
    float mu  = ssum[0] * (1.0f / 1024.0f);
    float var = ssq[0] * (1.0f / 1024.0f) - mu * mu;
    float rs  = rsqrtf(var + 1e-6f);
    float4 scv = ((const float4*)sc)[tid];
    float4 biv = ((const float4*)bi)[tid];
    float4 o;
    o.x = (v.x - mu) * rs * scv.x + biv.x;
    o.y = (v.y - mu) * rs * scv.y + biv.y;
    o.z = (v.z - mu) * rs * scv.z + biv.z;
    o.w = (v.w - mu) * rs * scv.w + biv.w;
    ((float4*)(out + s * D))[tid] = o;
}

// ---------------- tiled SGEMM: C[M,N] = f(A[M,K] * B[K,N]) ----------------
// 128x128 block tile, BK=16, 256 threads, 8x8 per-thread micro-tile.
__global__ __launch_bounds__(256) void sgemm_kernel(const float* __restrict__ A,
                                                    const float* __restrict__ B,
                                                    float* C, int N, int Kdim,
                                                    const float* __restrict__ bias,
                                                    const float* residual,
                                                    int relu, float scale) {
    __shared__ float As[16][128];
    __shared__ float Bs[16][128];
    int tid = threadIdx.x;
    int bm = blockIdx.y * 128;
    int bn = blockIdx.x * 128;
    int tx = tid & 15, ty = tid >> 4;

    float acc[8][8];
#pragma unroll
    for (int i = 0; i < 8; i++)
#pragma unroll
        for (int j = 0; j < 8; j++) acc[i][j] = 0.0f;

    const float* Aptr = A + (size_t)bm * Kdim;

    for (int k0 = 0; k0 < Kdim; k0 += 16) {
#pragma unroll
        for (int i = 0; i < 2; i++) {  // A tile: 128 rows x 16 cols -> transposed
            int idx = tid + i * 256;
            int r = idx >> 2, c4 = (idx & 3) << 2;
            float4 av = *(const float4*)(Aptr + (size_t)r * Kdim + k0 + c4);
            As[c4 + 0][r] = av.x; As[c4 + 1][r] = av.y;
            As[c4 + 2][r] = av.z; As[c4 + 3][r] = av.w;
        }
#pragma unroll
        for (int i = 0; i < 2; i++) {  // B tile: 16 rows x 128 cols
            int idx = tid + i * 256;
            int r = idx >> 5, c4 = (idx & 31) << 2;
            *(float4*)(&Bs[r][c4]) = *(const float4*)(B + (size_t)(k0 + r) * N + bn + c4);
        }
        __syncthreads();
#pragma unroll
        for (int kk = 0; kk < 16; kk++) {
            float a[8], b[8];
            *(float4*)(a)     = *(float4*)(&As[kk][ty * 8]);
            *(float4*)(a + 4) = *(float4*)(&As[kk][ty * 8 + 4]);
            *(float4*)(b)     = *(float4*)(&Bs[kk][tx * 8]);
            *(float4*)(b + 4) = *(float4*)(&Bs[kk][tx * 8 + 4]);
#pragma unroll
            for (int i = 0; i < 8; i++)
#pragma unroll
                for (int j = 0; j < 8; j++) acc[i][j] += a[i] * b[j];
        }
        __syncthreads();
    }

#pragma unroll
    for (int i = 0; i < 8; i++) {
        int row = bm + ty * 8 + i;
#pragma unroll
        for (int j = 0; j < 8; j++) {
            int col = bn + tx * 8 + j;
            float vv = acc[i][j] * scale;
            if (bias)     vv += bias[col];
            if (relu)     vv = fmaxf(vv, 0.0f);
            if (residual) vv += residual[(size_t)row * N + col];
            C[(size_t)row * N + col] = vv;
        }
    }
}

// ---------------- flash attention over band + global tiles ----------------
// Block: 256 threads, one (64-query tile, head). Key tiles of 64.
// Mask: allowed = |i-j|<=256 || i<64 || j<64 (N_GLOBAL=64 == tile width).
__global__ __launch_bounds__(256) void attn_kernel(const float* __restrict__ Qp,
                                                   const float* __restrict__ Kp,
                                                   const float* __restrict__ Vp,
                                                   float* __restrict__ O) {
    extern __shared__ float smem[];
    float* Qs = smem;               // [64][65]
    float* Ks = Qs + 64 * 65;       // [64][65]
    float* Vs = Ks + 64 * 65;       // [64][65]
    float* Ps = Vs + 64 * 65;       // [64][65]  scores -> probs
    float* mrow = Ps + 64 * 65;     // [64]
    float* lrow = mrow + 64;        // [64]
    float* cfac = lrow + 64;        // [64]

    const int h  = blockIdx.y;
    const int q0 = blockIdx.x * 64;
    const int tid = threadIdx.x;

    for (int i = tid; i < 64 * 64; i += 256) {
        int r = i >> 6, c = i & 63;
        Qs[r * 65 + c] = Qp[(q0 + r) * D + h * HD + c];
    }
    if (tid < 64) { mrow[tid] = -1e30f; lrow[tid] = 0.0f; }

    float acc[16];
#pragma unroll
    for (int r = 0; r < 16; r++) acc[r] = 0.0f;
    const int qi_c = tid >> 2;            // ctx phase: query row
    const int d0   = (tid & 3) * 16;      // ctx phase: dim group
    const int qi0  = (tid >> 4) << 2;     // score phase: 4x4 micro-tile
    const int kj0  = (tid & 15) << 2;

    int jlo, jhi;
    if (q0 < 64) { jlo = 0; jhi = 31; }   // global queries attend everything
    else {
        int lo = q0 - 256; jlo = lo > 0 ? (lo >> 6) : 0;
        int hi = (q0 + 63 + 256) >> 6; jhi = hi < 31 ? hi : 31;
    }
    const bool extra0 = (q0 >= 64) && (jlo > 0);  // global key tile (j<64)
    const int ntiles = (jhi - jlo + 1) + (extra0 ? 1 : 0);

    __syncthreads();

    for (int t = 0; t < ntiles; t++) {
        int jt = extra0 ? (t == 0 ? 0 : (jlo + t - 1)) : (jlo + t);
        int k0 = jt * 64;
        for (int i = tid; i < 64 * 64; i += 256) {
            int r = i >> 6, c = i & 63;
            Ks[r * 65 + c] = Kp[(k0 + r) * D + h * HD + c];
            Vs[r * 65 + c] = Vp[(k0 + r) * D + h * HD + c];
        }
        __syncthreads();

        // scores: each thread computes a 4x4 block of the 64x64 tile
        float sreg[4][4];
#pragma unroll
        for (int i = 0; i < 4; i++)
#pragma unroll
            for (int j = 0; j < 4; j++) sreg[i][j] = 0.0f;
#pragma unroll 8
        for (int kk = 0; kk < 64; kk++) {
            float qv[4], kv[4];
#pragma unroll
            for (int i = 0; i < 4; i++) qv[i] = Qs[(qi0 + i) * 65 + kk];
#pragma unroll
            for (int j = 0; j < 4; j++) kv[j] = Ks[(kj0 + j) * 65 + kk];
#pragma unroll
            for (int i = 0; i < 4; i++)
#pragma unroll
                for (int j = 0; j < 4; j++) sreg[i][j] += qv[i] * kv[j];
        }
        const bool tileAll = (q0 < 64) || (k0 < 64);
#pragma unroll
        for (int i = 0; i < 4; i++) {
            int gi = q0 + qi0 + i;
#pragma unroll
            for (int j = 0; j < 4; j++) {
                int gj = k0 + kj0 + j;
                int diff = gi - gj; if (diff < 0) diff = -diff;
                bool ok = tileAll || (diff <= 256);
                Ps[(qi0 + i) * 65 + kj0 + j] = ok ? sreg[i][j] : -1e30f;
            }
        }
        __syncthreads();

        // online softmax per query row (threads 0..63)
        if (tid < 64) {
            float m_old = mrow[tid];
            float mx = m_old;
#pragma unroll 8
            for (int j = 0; j < 64; j++) mx = fmaxf(mx, Ps[tid * 65 + j]);
            float corr = __expf(m_old - mx);
            float sum = 0.0f;
#pragma unroll 8
            for (int j = 0; j < 64; j++) {
                float sv = Ps[tid * 65 + j];
                float p = (sv < -1e29f) ? 0.0f : __expf(sv - mx);
                Ps[tid * 65 + j] = p;
                sum += p;
            }
            lrow[tid] = lrow[tid] * corr + sum;
            mrow[tid] = mx;
            cfac[tid] = corr;
        }
        __syncthreads();

        // ctx += P @ V  (each thread owns 16 dims of one query row)
        float corr = cfac[qi_c];
#pragma unroll
        for (int r = 0; r < 16; r++) acc[r] *= corr;
#pragma unroll 4
        for (int j = 0; j < 64; j++) {
            float p = Ps[qi_c * 65 + j];
#pragma unroll
            for (int r = 0; r < 16; r++) acc[r] += p * Vs[j * 65 + d0 + r];
        }
        __syncthreads();
    }

    float inv = 1.0f / lrow[qi_c];
#pragma unroll
    for (int r = 0; r < 16; r++)
        O[(q0 + qi_c) * D + h * HD + d0 + r] = acc[r] * inv;
}

// ---------------- launch ----------------
extern "C" void kernel_launch(void* const* d_in, const int* in_sizes, int n_in,
                              void* d_out, int out_size) {
    const int*   ids    = (const int*)d_in[0];
    // d_in[1] global_mask: structure is fixed by the problem (first 64 tokens
    // global, aligned with the 64-wide key tile) and baked into attn_kernel.
    const float* emb    = (const float*)d_in[2];
    const float* wq     = (const float*)d_in[3];
    const float* wk     = (const float*)d_in[4];
    const float* wv     = (const float*)d_in[5];
    const float* wo     = (const float*)d_in[6];
    const float* ln1_s  = (const float*)d_in[7];
    const float* ln1_b  = (const float*)d_in[8];
    const float* ln2_s  = (const float*)d_in[9];
    const float* ln2_b  = (const float*)d_in[10];
    const float* w1     = (const float*)d_in[11];
    const float* b1     = (const float*)d_in[12];
    const float* w2     = (const float*)d_in[13];
    const float* b2     = (const float*)d_in[14];
    const float* lnf_s  = (const float*)d_in[15];
    const float* lnf_b  = (const float*)d_in[16];
    float* out = (float*)d_out;

    void *px, *ph, *pq, *pk, *pv, *pc, *py;
    cudaGetSymbolAddress(&px, g_x);
    cudaGetSymbolAddress(&ph, g_h);
    cudaGetSymbolAddress(&pq, g_q);
    cudaGetSymbolAddress(&pk, g_k);
    cudaGetSymbolAddress(&pv, g_v);
    cudaGetSymbolAddress(&pc, g_ctx);
    cudaGetSymbolAddress(&py, g_y);
    float* x = (float*)px;  float* hbuf = (float*)ph;
    float* q = (float*)pq;  float* k = (float*)pk;  float* v = (float*)pv;
    float* ctx = (float*)pc; float* y = (float*)py;

    const int ATTN_SMEM = (4 * 64 * 65 + 3 * 64) * (int)sizeof(float);  // 67328 B
    cudaFuncSetAttribute(attn_kernel, cudaFuncAttributeMaxDynamicSharedMemorySize, ATTN_SMEM);

    embed_kernel<<<S, 256>>>(ids, emb, x);

    const float qscale = 0.125f;  // 1/sqrt(64)
    dim3 g_dd(D / 128, S / 128);     // 2048x1024x1024
    dim3 g_dm(MM / 128, S / 128);    // 2048x4096x1024
    dim3 g_md(D / 128, S / 128);     // 2048x1024x4096

    for (int l = 0; l < LAY; l++) {
        size_t woff = (size_t)l * D * D;          // 1024*1024
        ln_kernel<<<S, 256>>>(x, ln1_s + l * D, ln1_b + l * D, hbuf);
        sgemm_kernel<<<g_dd, 256>>>(hbuf, wq + woff, q, D, D, nullptr, nullptr, 0, qscale);
        sgemm_kernel<<<g_dd, 256>>>(hbuf, wk + woff, k, D, D, nullptr, nullptr, 0, 1.0f);
        sgemm_kernel<<<g_dd, 256>>>(hbuf, wv + woff, v, D, D, nullptr, nullptr, 0, 1.0f);
        attn_kernel<<<dim3(S / 64, H), 256, ATTN_SMEM>>>(q, k, v, ctx);
        sgemm_kernel<<<g_dd, 256>>>(ctx, wo + woff, x, D, D, nullptr, x, 0, 1.0f);
        ln_kernel<<<S, 256>>>(x, ln2_s + l * D, ln2_b + l * D, hbuf);
        sgemm_kernel<<<g_dm, 256>>>(hbuf, w1 + (size_t)l * D * MM, y, MM, D,
                                    b1 + (size_t)l * MM, nullptr, 1, 1.0f);
        sgemm_kernel<<<g_md, 256>>>(y, w2 + (size_t)l * MM * D, x, D, MM,
                                    b2 + (size_t)l * D, x, 0, 1.0f);
    }
    ln_kernel<<<S, 256>>>(x, lnf_s, lnf_b, out);
}

// round 3
// speedup vs baseline: 1.5394x; 1.5394x over previous
#include <cuda_runtime.h>
#include <cuda_bf16.h>
#include <math.h>
#include <stdint.h>

#define S   2048
#define D   1024
#define H   16
#define HD  64
#define MM  4096
#define LAY 4

// ---------------- scratch (device globals: no allocation allowed) ----------------
__device__ float g_x[S * D];
__device__ float g_h[S * D];
__device__ float g_q[S * D];
__device__ float g_k[S * D];
__device__ float g_v[S * D];
__device__ float g_ctx[S * D];
__device__ float g_y[S * MM];
// bf16 split buffers
__device__ __nv_bfloat16 g_a3[S * 3 * D];        // activations, K=1024 -> 3072
__device__ __nv_bfloat16 g_y3[S * 3 * MM];       // mlp hidden,  K=4096 -> 12288
__device__ __nv_bfloat16 g_wT[12 * 1024 * 1024]; // transposed split weights [N, 3K]

// ================= PTX helpers (portable sm_80-class) =================
__device__ __forceinline__ uint32_t smem_u32(const void* p) {
    uint32_t a;
    asm("{ .reg .u64 t; cvta.to.shared.u64 t, %1; cvt.u32.u64 %0, t; }" : "=r"(a) : "l"(p));
    return a;
}
__device__ __forceinline__ void cp16(uint32_t saddr, const void* g) {
    asm volatile("cp.async.cg.shared.global [%0], [%1], 16;" :: "r"(saddr), "l"(g));
}
#define CP_COMMIT() asm volatile("cp.async.commit_group;" ::: "memory")
#define CP_WAIT1()  asm volatile("cp.async.wait_group 1;" ::: "memory")

__device__ __forceinline__ void ldsm4(uint32_t* r, uint32_t a) {
    asm volatile("ldmatrix.sync.aligned.m8n8.x4.shared.b16 {%0,%1,%2,%3}, [%4];"
                 : "=r"(r[0]), "=r"(r[1]), "=r"(r[2]), "=r"(r[3]) : "r"(a));
}
__device__ __forceinline__ void mma16816(float* c, const uint32_t* a, uint32_t b0, uint32_t b1) {
    asm volatile("mma.sync.aligned.m16n8k16.row.col.f32.bf16.bf16.f32 "
                 "{%0,%1,%2,%3}, {%4,%5,%6,%7}, {%8,%9}, {%0,%1,%2,%3};"
                 : "+f"(c[0]), "+f"(c[1]), "+f"(c[2]), "+f"(c[3])
                 : "r"(a[0]), "r"(a[1]), "r"(a[2]), "r"(a[3]), "r"(b0), "r"(b1));
}

// ---------------- embedding + sinusoidal positional encoding ----------------
__global__ __launch_bounds__(256) void embed_kernel(const int* __restrict__ ids,
                                                    const float* __restrict__ emb,
                                                    float* __restrict__ x) {
    int s = blockIdx.x;
    int id = ids[s];
    const double c = -9.210340371976184 / 1024.0;  // -ln(10000)/D
    for (int d = threadIdx.x; d < D; d += 256) {
        int p2 = d & ~1;
        double freq = exp((double)p2 * c);
        double phase = (double)s * freq;
        double pe = (d & 1) ? cos(phase) : sin(phase);
        x[s * D + d] = emb[id * D + d] + (float)pe;
    }
}

// ---------------- LayerNorm ----------------
__global__ __launch_bounds__(256) void ln_kernel(const float* __restrict__ x,
                                                 const float* __restrict__ sc,
                                                 const float* __restrict__ bi,
                                                 float* __restrict__ out) {
    __shared__ float ssum[256], ssq[256];
    int s = blockIdx.x, tid = threadIdx.x;
    float4 v = ((const float4*)(x + s * D))[tid];
    ssum[tid] = v.x + v.y + v.z + v.w;
    ssq[tid]  = v.x * v.x + v.y * v.y + v.z * v.z + v.w * v.w;
    __syncthreads();
#pragma unroll
    for (int off = 128; off > 0; off >>= 1) {
        if (tid < off) { ssum[tid] += ssum[tid + off]; ssq[tid] += ssq[tid + off]; }
        __syncthreads();
    }
    float mu  = ssum[0] * (1.0f / 1024.0f);
    float var = ssq[0] * (1.0f / 1024.0f) - mu * mu;
    float rs  = rsqrtf(var + 1e-6f);
    float4 scv = ((const float4*)sc)[tid];
    float4 biv = ((const float4*)bi)[tid];
    float4 o;
    o.x = (v.x - mu) * rs * scv.x + biv.x;
    o.y = (v.y - mu) * rs * scv.y + biv.y;
    o.z = (v.z - mu) * rs * scv.z + biv.z;
    o.w = (v.w - mu) * rs * scv.w + biv.w;
    ((float4*)(out + s * D))[tid] = o;
}

// ---------------- fp32 -> split bf16 conversions ----------------
__device__ __forceinline__ void split2(float a, __nv_bfloat16& hi, __nv_bfloat16& lo) {
    hi = __float2bfloat16(a);
    lo = __float2bfloat16(a - __bfloat162float(hi));
}
// activations: A[M,K] fp32 -> A'[M,3K] bf16 = [hi | lo | hi]
__global__ __launch_bounds__(256) void convA_kernel(const float* __restrict__ A,
                                                    __nv_bfloat16* __restrict__ Ap, int K) {
    int r = blockIdx.x;
    const float* arow = A + (size_t)r * K;
    __nv_bfloat16* orow = Ap + (size_t)r * 3 * K;
    for (int c = threadIdx.x; c < K; c += 256) {
        __nv_bfloat16 hi, lo;
        split2(arow[c], hi, lo);
        orow[c] = hi; orow[K + c] = lo; orow[2 * K + c] = hi;
    }
}
// weights: W[K,N] fp32 -> Wt[N,3K] bf16 = [hi | hi | lo]  (transposed)
__global__ __launch_bounds__(256) void convW_kernel(const float* __restrict__ W,
                                                    __nv_bfloat16* __restrict__ Wt,
                                                    int K, int N) {
    __shared__ float t[32][33];
    int k0 = blockIdx.x * 32, n0 = blockIdx.y * 32;
    int tx = threadIdx.x & 31, ty = threadIdx.x >> 5;   // 32 x 8
#pragma unroll
    for (int i = 0; i < 4; i++)
        t[ty + i * 8][tx] = W[(size_t)(k0 + ty + i * 8) * N + n0 + tx];
    __syncthreads();
#pragma unroll
    for (int i = 0; i < 4; i++) {
        int n = n0 + ty + i * 8, k = k0 + tx;
        __nv_bfloat16 hi, lo;
        split2(t[tx][ty + i * 8], hi, lo);
        __nv_bfloat16* orow = Wt + (size_t)n * 3 * K;
        orow[k] = hi; orow[K + k] = hi; orow[2 * K + k] = lo;
    }
}

// ---------------- HMMA bf16 GEMM: C[M,N] = f(A'[M,K3] . Bt[N,K3]^T) ----------
// CTA 128x128, 8 warps (4x2), warp tile 32x64, BK=32, cp.async double buffer.
// SMEM tiles padded to 40 bf16/row (80B) -> conflict-free ldmatrix.
__global__ __launch_bounds__(256) void tc_gemm_kernel(const __nv_bfloat16* __restrict__ A,
                                                      const __nv_bfloat16* __restrict__ Bt,
                                                      float* __restrict__ C, int N, int K3,
                                                      const float* __restrict__ bias,
                                                      const float* residual,
                                                      int relu, float scale) {
    __shared__ __nv_bfloat16 As[2][128 * 40];
    __shared__ __nv_bfloat16 Bs[2][128 * 40];
    const int tid = threadIdx.x, lane = tid & 31, wid = tid >> 5;
    const int bm = blockIdx.y * 128, bn = blockIdx.x * 128;
    const int wm = (wid >> 1) * 32, wn = (wid & 1) * 64;
    const size_t rs = (size_t)K3 * 2;  // row stride bytes
    const char* Ag = (const char*)A + (size_t)bm * rs;
    const char* Bg = (const char*)Bt + (size_t)bn * rs;
    const uint32_t asb = smem_u32(As), bsb = smem_u32(Bs);

    // cp.async chunk coords for this thread (2 chunks per tile)
    const int r0c = tid >> 2, cb0 = (tid & 3) * 16;          // chunks 0..255
    const int r1c = (tid + 256) >> 2, cb1 = ((tid + 256) & 3) * 16;

    // ldmatrix lane offsets (bytes within a stage)
    uint32_t a_off[2], b_off[4];
#pragma unroll
    for (int mi = 0; mi < 2; mi++)
        a_off[mi] = (uint32_t)((wm + mi * 16 + (lane & 15)) * 80 + ((lane >> 4) * 16));
#pragma unroll
    for (int pi = 0; pi < 4; pi++) {
        int row = wn + pi * 16 + (lane & 7) + ((lane >> 4) << 3);
        int colb = ((lane >> 3) & 1) * 16;
        b_off[pi] = (uint32_t)(row * 80 + colb);
    }

    float acc[2][8][4];
#pragma unroll
    for (int mi = 0; mi < 2; mi++)
#pragma unroll
        for (int ni = 0; ni < 8; ni++)
#pragma unroll
            for (int j = 0; j < 4; j++) acc[mi][ni][j] = 0.0f;

    auto load_stage = [&](int buf, int kt) {
        size_t gk = (size_t)kt * 64;  // bytes
        uint32_t sa = asb + buf * 10240, sb2 = bsb + buf * 10240;
        cp16(sa + r0c * 80 + cb0, Ag + (size_t)r0c * rs + gk + cb0);
        cp16(sa + r1c * 80 + cb1, Ag + (size_t)r1c * rs + gk + cb1);
        cp16(sb2 + r0c * 80 + cb0, Bg + (size_t)r0c * rs + gk + cb0);
        cp16(sb2 + r1c * 80 + cb1, Bg + (size_t)r1c * rs + gk + cb1);
    };

    const int KT = K3 >> 5;
    load_stage(0, 0); CP_COMMIT();
    load_stage(1, 1); CP_COMMIT();

    for (int kt = 0; kt < KT; kt++) {
        const int buf = kt & 1;
        CP_WAIT1();
        __syncthreads();
        const uint32_t ab = asb + buf * 10240, bb = bsb + buf * 10240;
#pragma unroll
        for (int ks = 0; ks < 2; ks++) {
            uint32_t a[2][4];
            ldsm4(a[0], ab + a_off[0] + ks * 32);
            ldsm4(a[1], ab + a_off[1] + ks * 32);
#pragma unroll
            for (int pi = 0; pi < 4; pi++) {
                uint32_t b[4];
                ldsm4(b, bb + b_off[pi] + ks * 32);
                mma16816(acc[0][2 * pi],     a[0], b[0], b[1]);
                mma16816(acc[0][2 * pi + 1], a[0], b[2], b[3]);
                mma16816(acc[1][2 * pi],     a[1], b[0], b[1]);
                mma16816(acc[1][2 * pi + 1], a[1], b[2], b[3]);
            }
        }
        __syncthreads();
        if (kt + 2 < KT) load_stage(buf, kt + 2);
        CP_COMMIT();
    }

    // epilogue: c-frag mapping m16n8 -> (row = lane/4 [+8], col = (lane%4)*2)
    const int erow = lane >> 2, ecol = (lane & 3) * 2;
#pragma unroll
    for (int mi = 0; mi < 2; mi++) {
#pragma unroll
        for (int ni = 0; ni < 8; ni++) {
            float* c = acc[mi][ni];
            int col = bn + wn + ni * 8 + ecol;
#pragma unroll
            for (int half = 0; half < 2; half++) {
                int row = bm + wm + mi * 16 + erow + half * 8;
                float vx = c[half * 2 + 0] * scale;
                float vy = c[half * 2 + 1] * scale;
                if (bias)  { vx += bias[col]; vy += bias[col + 1]; }
                if (relu)  { vx = fmaxf(vx, 0.f); vy = fmaxf(vy, 0.f); }
                if (residual) {
                    const float2 rv = *(const float2*)(residual + (size_t)row * N + col);
                    vx += rv.x; vy += rv.y;
                }
                float2 o; o.x = vx; o.y = vy;
                *(float2*)(C + (size_t)row * N + col) = o;
            }
        }
    }
}

// ---------------- flash attention over band + global tiles ----------------
__global__ __launch_bounds__(256) void attn_kernel(const float* __restrict__ Qp,
                                                   const float* __restrict__ Kp,
                                                   const float* __restrict__ Vp,
                                                   float* __restrict__ O) {
    extern __shared__ float fsm[];
    float* Qs = fsm;
    float* Ks = Qs + 64 * 65;
    float* Vs = Ks + 64 * 65;
    float* Ps = Vs + 64 * 65;
    float* mrow = Ps + 64 * 65;
    float* lrow = mrow + 64;
    float* cfac = lrow + 64;

    const int h  = blockIdx.y;
    const int q0 = blockIdx.x * 64;
    const int tid = threadIdx.x;

    for (int i = tid; i < 64 * 64; i += 256) {
        int r = i >> 6, c = i & 63;
        Qs[r * 65 + c] = Qp[(q0 + r) * D + h * HD + c];
    }
    if (tid < 64) { mrow[tid] = -1e30f; lrow[tid] = 0.0f; }

    float acc[16];
#pragma unroll
    for (int r = 0; r < 16; r++) acc[r] = 0.0f;
    const int qi_c = tid >> 2;
    const int d0   = (tid & 3) * 16;
    const int qi0  = (tid >> 4) << 2;
    const int kj0  = (tid & 15) << 2;

    int jlo, jhi;
    if (q0 < 64) { jlo = 0; jhi = 31; }
    else {
        int lo = q0 - 256; jlo = lo > 0 ? (lo >> 6) : 0;
        int hi = (q0 + 63 + 256) >> 6; jhi = hi < 31 ? hi : 31;
    }
    const bool extra0 = (q0 >= 64) && (jlo > 0);
    const int ntiles = (jhi - jlo + 1) + (extra0 ? 1 : 0);

    __syncthreads();

    for (int t = 0; t < ntiles; t++) {
        int jt = extra0 ? (t == 0 ? 0 : (jlo + t - 1)) : (jlo + t);
        int k0 = jt * 64;
        for (int i = tid; i < 64 * 64; i += 256) {
            int r = i >> 6, c = i & 63;
            Ks[r * 65 + c] = Kp[(k0 + r) * D + h * HD + c];
            Vs[r * 65 + c] = Vp[(k0 + r) * D + h * HD + c];
        }
        __syncthreads();

        float sreg[4][4];
#pragma unroll
        for (int i = 0; i < 4; i++)
#pragma unroll
            for (int j = 0; j < 4; j++) sreg[i][j] = 0.0f;
#pragma unroll 8
        for (int kk = 0; kk < 64; kk++) {
            float qv[4], kv[4];
#pragma unroll
            for (int i = 0; i < 4; i++) qv[i] = Qs[(qi0 + i) * 65 + kk];
#pragma unroll
            for (int j = 0; j < 4; j++) kv[j] = Ks[(kj0 + j) * 65 + kk];
#pragma unroll
            for (int i = 0; i < 4; i++)
#pragma unroll
                for (int j = 0; j < 4; j++) sreg[i][j] += qv[i] * kv[j];
        }
        const bool tileAll = (q0 < 64) || (k0 < 64);
#pragma unroll
        for (int i = 0; i < 4; i++) {
            int gi = q0 + qi0 + i;
#pragma unroll
            for (int j = 0; j < 4; j++) {
                int gj = k0 + kj0 + j;
                int diff = gi - gj; if (diff < 0) diff = -diff;
                bool ok = tileAll || (diff <= 256);
                Ps[(qi0 + i) * 65 + kj0 + j] = ok ? sreg[i][j] : -1e30f;
            }
        }
        __syncthreads();

        if (tid < 64) {
            float m_old = mrow[tid];
            float mx = m_old;
#pragma unroll 8
            for (int j = 0; j < 64; j++) mx = fmaxf(mx, Ps[tid * 65 + j]);
            float corr = __expf(m_old - mx);
            float sum = 0.0f;
#pragma unroll 8
            for (int j = 0; j < 64; j++) {
                float sv = Ps[tid * 65 + j];
                float p = (sv < -1e29f) ? 0.0f : __expf(sv - mx);
                Ps[tid * 65 + j] = p;
                sum += p;
            }
            lrow[tid] = lrow[tid] * corr + sum;
            mrow[tid] = mx;
            cfac[tid] = corr;
        }
        __syncthreads();

        float corr = cfac[qi_c];
#pragma unroll
        for (int r = 0; r < 16; r++) acc[r] *= corr;
#pragma unroll 4
        for (int j = 0; j < 64; j++) {
            float p = Ps[qi_c * 65 + j];
#pragma unroll
            for (int r = 0; r < 16; r++) acc[r] += p * Vs[j * 65 + d0 + r];
        }
        __syncthreads();
    }

    float inv = 1.0f / lrow[qi_c];
#pragma unroll
    for (int r = 0; r < 16; r++)
        O[(q0 + qi_c) * D + h * HD + d0 + r] = acc[r] * inv;
}

// ---------------- launch ----------------
extern "C" void kernel_launch(void* const* d_in, const int* in_sizes, int n_in,
                              void* d_out, int out_size) {
    const int*   ids    = (const int*)d_in[0];
    const float* emb    = (const float*)d_in[2];
    const float* wq     = (const float*)d_in[3];
    const float* wk     = (const float*)d_in[4];
    const float* wv     = (const float*)d_in[5];
    const float* wo     = (const float*)d_in[6];
    const float* ln1_s  = (const float*)d_in[7];
    const float* ln1_b  = (const float*)d_in[8];
    const float* ln2_s  = (const float*)d_in[9];
    const float* ln2_b  = (const float*)d_in[10];
    const float* w1     = (const float*)d_in[11];
    const float* b1     = (const float*)d_in[12];
    const float* w2     = (const float*)d_in[13];
    const float* b2     = (const float*)d_in[14];
    const float* lnf_s  = (const float*)d_in[15];
    const float* lnf_b  = (const float*)d_in[16];
    float* out = (float*)d_out;

    void *px, *ph, *pq, *pk, *pv, *pc, *py, *pa3, *py3, *pwT;
    cudaGetSymbolAddress(&px, g_x);
    cudaGetSymbolAddress(&ph, g_h);
    cudaGetSymbolAddress(&pq, g_q);
    cudaGetSymbolAddress(&pk, g_k);
    cudaGetSymbolAddress(&pv, g_v);
    cudaGetSymbolAddress(&pc, g_ctx);
    cudaGetSymbolAddress(&py, g_y);
    cudaGetSymbolAddress(&pa3, g_a3);
    cudaGetSymbolAddress(&py3, g_y3);
    cudaGetSymbolAddress(&pwT, g_wT);
    float* x = (float*)px;  float* hbuf = (float*)ph;
    float* q = (float*)pq;  float* k = (float*)pk;  float* v = (float*)pv;
    float* ctx = (float*)pc; float* y = (float*)py;
    __nv_bfloat16* a3 = (__nv_bfloat16*)pa3;
    __nv_bfloat16* y3 = (__nv_bfloat16*)py3;
    __nv_bfloat16* wT = (__nv_bfloat16*)pwT;

    const int ATTN_SMEM = (4 * 64 * 65 + 3 * 64) * (int)sizeof(float);
    cudaFuncSetAttribute(attn_kernel, cudaFuncAttributeMaxDynamicSharedMemorySize, ATTN_SMEM);

    embed_kernel<<<S, 256>>>(ids, emb, x);

    const float qscale = 0.125f;  // 1/sqrt(64)
    dim3 g_dd(D / 128, S / 128);      // N=1024
    dim3 g_dm(MM / 128, S / 128);     // N=4096
    dim3 cw_dd(D / 32, D / 32);       // K=1024, N=1024
    dim3 cw_dm(D / 32, MM / 32);      // K=1024, N=4096
    dim3 cw_md(MM / 32, D / 32);      // K=4096, N=1024

    for (int l = 0; l < LAY; l++) {
        size_t woff = (size_t)l * D * D;
        ln_kernel<<<S, 256>>>(x, ln1_s + l * D, ln1_b + l * D, hbuf);
        convA_kernel<<<S, 256>>>(hbuf, a3, D);
        convW_kernel<<<cw_dd, 256>>>(wq + woff, wT, D, D);
        tc_gemm_kernel<<<g_dd, 256>>>(a3, wT, q, D, 3 * D, nullptr, nullptr, 0, qscale);
        convW_kernel<<<cw_dd, 256>>>(wk + woff, wT, D, D);
        tc_gemm_kernel<<<g_dd, 256>>>(a3, wT, k, D, 3 * D, nullptr, nullptr, 0, 1.0f);
        convW_kernel<<<cw_dd, 256>>>(wv + woff, wT, D, D);
        tc_gemm_kernel<<<g_dd, 256>>>(a3, wT, v, D, 3 * D, nullptr, nullptr, 0, 1.0f);
        attn_kernel<<<dim3(S / 64, H), 256, ATTN_SMEM>>>(q, k, v, ctx);
        convA_kernel<<<S, 256>>>(ctx, a3, D);
        convW_kernel<<<cw_dd, 256>>>(wo + woff, wT, D, D);
        tc_gemm_kernel<<<g_dd, 256>>>(a3, wT, x, D, 3 * D, nullptr, x, 0, 1.0f);
        ln_kernel<<<S, 256>>>(x, ln2_s + l * D, ln2_b + l * D, hbuf);
        convA_kernel<<<S, 256>>>(hbuf, a3, D);
        convW_kernel<<<cw_dm, 256>>>(w1 + (size_t)l * D * MM, wT, D, MM);
        tc_gemm_kernel<<<g_dm, 256>>>(a3, wT, y, MM, 3 * D,
                                      b1 + (size_t)l * MM, nullptr, 1, 1.0f);
        convA_kernel<<<S, 256>>>(y, y3, MM);
        convW_kernel<<<cw_md, 256>>>(w2 + (size_t)l * MM * D, wT, MM, D);
        tc_gemm_kernel<<<g_dd, 256>>>(y3, wT, x, D, 3 * MM,
                                      b2 + (size_t)l * D, x, 0, 1.0f);
    }
    ln_kernel<<<S, 256>>>(x, lnf_s, lnf_b, out);
}